// round 6
// baseline (speedup 1.0000x reference)
#include <cuda_runtime.h>
#include <cuda_bf16.h>
#include <math.h>
#include <stdint.h>

// ---------------------------------------------------------------------------
// DistMultDecoder: out[e] = sigmoid( z[src_e] . (W + W^T) . z[dst_e] )
//   Wsym = W + W^T (symmetric) ; Y = Z @ Wsym ; out[e] = sigmoid(dot(Y[src], Z[dst]))
// Persistent GEMM via mma.sync bf16 with 2-term Dekker split:
//   Y = Zh*Wh + Zh*Wl + Zl*Wh   (fp32 accumulate, err ~2^-18)
// ---------------------------------------------------------------------------

#define HID 128
#define MAX_NODES 100000
#define PAD_W 68   // words per smem row = 136 bf16 (128+8 pad) -> conflict-free frags

__device__ float g_Y[(size_t)MAX_NODES * HID];
__device__ int   g_is64;

// ---------------- kernel 0: detect index dtype (int64 vs int32) ------------
__global__ void detect_kernel(const int* __restrict__ ei32) {
    if (threadIdx.x == 0) {
        int s = 0;
        #pragma unroll
        for (int i = 1; i < 64; i += 2) s |= ei32[i];
        g_is64 = (s == 0) ? 1 : 0;
    }
}

// ---------------- kernel 1: persistent Y = Z @ (W+W^T) ----------------------
#define MMA16816(D, A0, A1, A2, A3, B0, B1)                                   \
    asm volatile("mma.sync.aligned.m16n8k16.row.col.f32.bf16.bf16.f32 "       \
                 "{%0,%1,%2,%3}, {%4,%5,%6,%7}, {%8,%9}, {%0,%1,%2,%3};"      \
                 : "+f"(D[0]), "+f"(D[1]), "+f"(D[2]), "+f"(D[3])             \
                 : "r"(A0), "r"(A1), "r"(A2), "r"(A3), "r"(B0), "r"(B1))

__global__ __launch_bounds__(256) void gemm_mma_persist(const float* __restrict__ Z,
                                                        const float* __restrict__ W,
                                                        int nrows, int ntiles) {
    extern __shared__ __align__(16) uint32_t sh[];
    uint32_t* AH = sh;                      // 128 x 68 words (bf16x2)
    uint32_t* AL = sh + 128 * PAD_W;
    uint32_t* WH = sh + 2 * 128 * PAD_W;
    uint32_t* WL = sh + 3 * 128 * PAD_W;

    int tid = threadIdx.x;

    // ---- one-time prologue: Wsym = W + W^T, split to bf16 hi/lo in smem ----
    // word idx: row n = idx>>6, k pair = (idx&63)*2
    #pragma unroll
    for (int i = 0; i < 32; i++) {
        int idx = tid + 256 * i;             // 0..8191
        int n   = idx >> 6;
        int k0  = (idx & 63) * 2;
        float a0 = W[n * HID + k0]     + W[k0 * HID + n];
        float a1 = W[n * HID + k0 + 1] + W[(k0 + 1) * HID + n];
        __nv_bfloat162 h = __floats2bfloat162_rn(a0, a1);
        __nv_bfloat162 l = __floats2bfloat162_rn(a0 - __bfloat162float(h.x),
                                                 a1 - __bfloat162float(h.y));
        WH[n * PAD_W + (idx & 63)] = *(uint32_t*)&h;
        WL[n * PAD_W + (idx & 63)] = *(uint32_t*)&l;
    }

    int lane = tid & 31, w = tid >> 5;
    int g = lane >> 2, t = lane & 3;
    int r0 = (w & 3) * 32;        // warp row base within CTA tile
    int n0 = (w >> 2) * 64;       // warp col base

    // A-convert addressing (fixed per thread)
    int arow = tid >> 1;
    int ac0  = (tid & 1) * 64;

    for (int tile = blockIdx.x; tile < ntiles; tile += gridDim.x) {
        // ---- load Z tile, split to bf16 hi/lo in smem ----
        {
            int grow = tile * 128 + arow;
            bool valid = (grow < nrows);
            const float4* zr = (const float4*)(Z + (size_t)(valid ? grow : 0) * HID + ac0);
            #pragma unroll
            for (int j = 0; j < 16; j++) {
                float4 v = zr[j];
                if (!valid) v = make_float4(0.f, 0.f, 0.f, 0.f);
                __nv_bfloat162 h0 = __floats2bfloat162_rn(v.x, v.y);
                __nv_bfloat162 h1 = __floats2bfloat162_rn(v.z, v.w);
                __nv_bfloat162 l0 = __floats2bfloat162_rn(v.x - __bfloat162float(h0.x),
                                                          v.y - __bfloat162float(h0.y));
                __nv_bfloat162 l1 = __floats2bfloat162_rn(v.z - __bfloat162float(h1.x),
                                                          v.w - __bfloat162float(h1.y));
                int wofs = arow * PAD_W + ((ac0 + 4 * j) >> 1);
                AH[wofs]     = *(uint32_t*)&h0;
                AH[wofs + 1] = *(uint32_t*)&h1;
                AL[wofs]     = *(uint32_t*)&l0;
                AL[wofs + 1] = *(uint32_t*)&l1;
            }
        }
        __syncthreads();   // A (and W on first iter) visible to all

        float d[2][8][4];
        #pragma unroll
        for (int m = 0; m < 2; m++)
            #pragma unroll
            for (int n = 0; n < 8; n++)
                #pragma unroll
                for (int q = 0; q < 4; q++) d[m][n][q] = 0.f;

        #pragma unroll 2
        for (int ks = 0; ks < 8; ks++) {
            int kb = ks * 8 + t;
            uint32_t ah[2][4], al[2][4];
            #pragma unroll
            for (int m = 0; m < 2; m++) {
                int rb = (r0 + 16 * m + g) * PAD_W + kb;
                ah[m][0] = AH[rb];              ah[m][1] = AH[rb + 8 * PAD_W];
                ah[m][2] = AH[rb + 4];          ah[m][3] = AH[rb + 8 * PAD_W + 4];
                al[m][0] = AL[rb];              al[m][1] = AL[rb + 8 * PAD_W];
                al[m][2] = AL[rb + 4];          al[m][3] = AL[rb + 8 * PAD_W + 4];
            }
            #pragma unroll
            for (int n = 0; n < 8; n++) {
                int nb = (n0 + 8 * n + g) * PAD_W + kb;
                uint32_t bh0 = WH[nb], bh1 = WH[nb + 4];
                uint32_t bl0 = WL[nb], bl1 = WL[nb + 4];
                #pragma unroll
                for (int m = 0; m < 2; m++) {
                    MMA16816(d[m][n], ah[m][0], ah[m][1], ah[m][2], ah[m][3], bh0, bh1);
                    MMA16816(d[m][n], ah[m][0], ah[m][1], ah[m][2], ah[m][3], bl0, bl1);
                    MMA16816(d[m][n], al[m][0], al[m][1], al[m][2], al[m][3], bh0, bh1);
                }
            }
        }

        // ---- epilogue: d -> g_Y ----
        int rowbase = tile * 128 + r0 + g;
        #pragma unroll
        for (int m = 0; m < 2; m++) {
            int r = rowbase + 16 * m;
            #pragma unroll
            for (int n = 0; n < 8; n++) {
                int c = n0 + 8 * n + 2 * t;
                if (r < nrows)
                    *(float2*)(g_Y + (size_t)r * HID + c) = make_float2(d[m][n][0], d[m][n][1]);
                if (r + 8 < nrows)
                    *(float2*)(g_Y + (size_t)(r + 8) * HID + c) = make_float2(d[m][n][2], d[m][n][3]);
            }
        }
        __syncthreads();   // all warps done reading A before next overwrite
    }
}

// ------------------- kernel 2: per-edge gather + dot + sigmoid --------------
__global__ __launch_bounds__(256) void edge_kernel(const void* __restrict__ ei,
                                                   const float* __restrict__ Z,
                                                   float* __restrict__ out, int E) {
    const unsigned FULL = 0xFFFFFFFFu;
    int gtid  = blockIdx.x * blockDim.x + threadIdx.x;
    int warp  = gtid >> 5;
    int lane  = gtid & 31;
    int grp   = lane >> 3;
    int sub   = lane & 7;

    long long e0 = (long long)warp * 4;
    if (e0 >= E) return;

    long long myidx = 0;
    int is64 = g_is64;
    if (lane < 8) {
        long long e = e0 + (lane & 3);
        if (e >= E) e = 0;
        size_t off = (lane < 4) ? (size_t)e : (size_t)E + (size_t)e;
        if (is64) myidx = ((const long long*)ei)[off];
        else      myidx = ((const int*)ei)[off];
    }
    long long src = __shfl_sync(FULL, myidx, grp);
    long long dst = __shfl_sync(FULL, myidx, 4 + grp);

    const float4* Ya = (const float4*)(g_Y + (size_t)src * HID);
    const float4* Zb = (const float4*)(Z   + (size_t)dst * HID);

    float4 a0 = Ya[sub];        float4 b0 = Zb[sub];
    float4 a1 = Ya[sub + 8];    float4 b1 = Zb[sub + 8];
    float4 a2 = Ya[sub + 16];   float4 b2 = Zb[sub + 16];
    float4 a3 = Ya[sub + 24];   float4 b3 = Zb[sub + 24];

    float v = a0.x * b0.x + a0.y * b0.y + a0.z * b0.z + a0.w * b0.w;
    v += a1.x * b1.x + a1.y * b1.y + a1.z * b1.z + a1.w * b1.w;
    v += a2.x * b2.x + a2.y * b2.y + a2.z * b2.z + a2.w * b2.w;
    v += a3.x * b3.x + a3.y * b3.y + a3.z * b3.z + a3.w * b3.w;

    v += __shfl_xor_sync(FULL, v, 1);
    v += __shfl_xor_sync(FULL, v, 2);
    v += __shfl_xor_sync(FULL, v, 4);

    float vg = __shfl_sync(FULL, v, lane << 3);
    if (lane < 4) {
        long long e = e0 + lane;
        if (e < E) out[e] = 1.0f / (1.0f + expf(-vg));
    }
}

// ---------------------------------------------------------------------------
extern "C" void kernel_launch(void* const* d_in, const int* in_sizes, int n_in,
                              void* d_out, int out_size) {
    // Map inputs by element count: W = 16384; z = largest; edge_index = the rest.
    int wi = -1;
    for (int i = 0; i < n_in; i++) if (in_sizes[i] == HID * HID) { wi = i; break; }
    int zi = -1;
    for (int i = 0; i < n_in; i++) {
        if (i == wi) continue;
        if (zi < 0 || in_sizes[i] > in_sizes[zi]) zi = i;
    }
    int eii = -1;
    for (int i = 0; i < n_in; i++) if (i != wi && i != zi) { eii = i; break; }

    const float* W  = (const float*)d_in[wi];
    const float* z  = (const float*)d_in[zi];
    const void*  ei = d_in[eii];

    float* out = (float*)d_out;
    int nrows = in_sizes[zi] / HID;
    int E     = in_sizes[eii] / 2;

    detect_kernel<<<1, 32>>>((const int*)ei);

    int ntiles = (nrows + 127) / 128;
    int gblocks = ntiles < 148 ? ntiles : 148;
    int smem = 4 * 128 * PAD_W * (int)sizeof(uint32_t);   // 139264 B
    cudaFuncSetAttribute(gemm_mma_persist, cudaFuncAttributeMaxDynamicSharedMemorySize, smem);
    gemm_mma_persist<<<gblocks, 256, smem>>>(z, W, nrows, ntiles);

    int eblocks = (E + 31) / 32;
    edge_kernel<<<eblocks, 256>>>(ei, z, out, E);
}

// round 7
// speedup vs baseline: 1.0793x; 1.0793x over previous
#include <cuda_runtime.h>
#include <cuda_bf16.h>
#include <math.h>
#include <stdint.h>

// ---------------------------------------------------------------------------
// DistMultDecoder: out[e] = sigmoid( z[src_e] . (W + W^T) . z[dst_e] )
//   Wsym = W + W^T (symmetric) ; Y = Z @ Wsym ; out[e] = sigmoid(dot(Y[src], Z[dst]))
// GEMM: mma.sync bf16, 2-term Dekker split  Y = Zh*Wh + Zh*Wl + Zl*Wh.
// A fragments loaded DIRECTLY from global Z (float2, coalesced 32B sectors),
// converted in registers -> no A smem stage, smem = W hi/lo only (2 CTAs/SM).
// ---------------------------------------------------------------------------

#define HID 128
#define MAX_NODES 100000
#define PAD_W 68   // words/row: frag LDS bank = (4g+t) mod 32, conflict-free

__device__ float g_Y[(size_t)MAX_NODES * HID];
__device__ int   g_is64;
__device__ __nv_bfloat16 g_Wh[HID * HID];   // Wsym hi, row-major [n][k]
__device__ __nv_bfloat16 g_Wl[HID * HID];   // Wsym lo

// ------- kernel 1: Wsym = W + W^T -> bf16 hi/lo ; + index-dtype detect ------
__global__ void symm_kernel(const float* __restrict__ W, const int* __restrict__ ei32) {
    if (blockIdx.x == 0 && threadIdx.x == 0) {
        int s = 0;
        #pragma unroll
        for (int i = 1; i < 64; i += 2) s |= ei32[i];
        g_is64 = (s == 0) ? 1 : 0;          // int64 LE small values: odd words all 0
    }
    int i = blockIdx.x * blockDim.x + threadIdx.x;   // 0..16383
    int n = i >> 7, k = i & 127;
    float v = W[n * HID + k] + W[k * HID + n];       // Wsym[n][k]
    __nv_bfloat16 hi = __float2bfloat16(v);
    __nv_bfloat16 lo = __float2bfloat16(v - __bfloat162float(hi));
    g_Wh[i] = hi;
    g_Wl[i] = lo;
}

// ---------------- kernel 2: Y = Z @ Wsym via mma.sync bf16 ------------------
#define MMA16816(D, A0, A1, A2, A3, B0, B1)                                   \
    asm volatile("mma.sync.aligned.m16n8k16.row.col.f32.bf16.bf16.f32 "       \
                 "{%0,%1,%2,%3}, {%4,%5,%6,%7}, {%8,%9}, {%0,%1,%2,%3};"      \
                 : "+f"(D[0]), "+f"(D[1]), "+f"(D[2]), "+f"(D[3])             \
                 : "r"(A0), "r"(A1), "r"(A2), "r"(A3), "r"(B0), "r"(B1))

__device__ __forceinline__ uint32_t bf2_hi(float2 p) {
    __nv_bfloat162 h = __floats2bfloat162_rn(p.x, p.y);
    return *(uint32_t*)&h;
}
__device__ __forceinline__ uint32_t bf2_lo(float2 p, uint32_t hbits) {
    __nv_bfloat162 h = *(__nv_bfloat162*)&hbits;
    __nv_bfloat162 l = __floats2bfloat162_rn(p.x - __bfloat162float(h.x),
                                             p.y - __bfloat162float(h.y));
    return *(uint32_t*)&l;
}

__global__ __launch_bounds__(256) void gemm_mma_kernel(const float* __restrict__ Z, int nrows) {
    extern __shared__ __align__(16) uint32_t sh[];
    uint32_t* WH = sh;                    // 128 x 68 words (bf16x2)
    uint32_t* WL = sh + 128 * PAD_W;

    int tid = threadIdx.x;

    // ---- stage W hi/lo into padded smem (8192 words each, coalesced) ----
    {
        const uint32_t* gwh = (const uint32_t*)g_Wh;
        const uint32_t* gwl = (const uint32_t*)g_Wl;
        #pragma unroll
        for (int i = 0; i < 32; i++) {
            int idx  = tid + 256 * i;        // 0..8191
            int row  = idx >> 6;
            int word = idx & 63;
            WH[row * PAD_W + word] = gwh[idx];
            WL[row * PAD_W + word] = gwl[idx];
        }
    }
    __syncthreads();

    int lane = tid & 31, w = tid >> 5;
    int g = lane >> 2, t = lane & 3;
    int r0 = (w & 3) * 32;        // warp row base within CTA tile
    int n0 = (w >> 2) * 64;       // warp col base

    // Per-thread A rows (clamped for OOB; garbage accumulators never stored)
    int base = blockIdx.x * 128 + r0 + g;
    int rA[4] = { base, base + 8, base + 16, base + 24 };   // m0:g,g+8  m1:+16,+24
    const float* zp[4];
    #pragma unroll
    for (int q = 0; q < 4; q++) {
        int r = rA[q] < nrows ? rA[q] : (nrows - 1);
        zp[q] = Z + (size_t)r * HID + 2 * t;
    }

    float d[2][8][4];
    #pragma unroll
    for (int m = 0; m < 2; m++)
        #pragma unroll
        for (int n = 0; n < 8; n++)
            #pragma unroll
            for (int q = 0; q < 4; q++) d[m][n][q] = 0.f;

    #pragma unroll
    for (int ks = 0; ks < 8; ks++) {
        int kb = ks * 16;
        // A fragments direct from global: rows {g, g+8} x k {2t, 2t+8}, per m
        float2 p00 = *(const float2*)(zp[0] + kb);       // m0 row g,   k 2t
        float2 p01 = *(const float2*)(zp[0] + kb + 8);   // m0 row g,   k 2t+8
        float2 p10 = *(const float2*)(zp[1] + kb);       // m0 row g+8
        float2 p11 = *(const float2*)(zp[1] + kb + 8);
        float2 q00 = *(const float2*)(zp[2] + kb);       // m1 row g+16
        float2 q01 = *(const float2*)(zp[2] + kb + 8);
        float2 q10 = *(const float2*)(zp[3] + kb);       // m1 row g+24
        float2 q11 = *(const float2*)(zp[3] + kb + 8);

        uint32_t ah[2][4], al[2][4];
        ah[0][0] = bf2_hi(p00);  ah[0][1] = bf2_hi(p10);
        ah[0][2] = bf2_hi(p01);  ah[0][3] = bf2_hi(p11);
        ah[1][0] = bf2_hi(q00);  ah[1][1] = bf2_hi(q10);
        ah[1][2] = bf2_hi(q01);  ah[1][3] = bf2_hi(q11);
        al[0][0] = bf2_lo(p00, ah[0][0]);  al[0][1] = bf2_lo(p10, ah[0][1]);
        al[0][2] = bf2_lo(p01, ah[0][2]);  al[0][3] = bf2_lo(p11, ah[0][3]);
        al[1][0] = bf2_lo(q00, ah[1][0]);  al[1][1] = bf2_lo(q10, ah[1][1]);
        al[1][2] = bf2_lo(q01, ah[1][2]);  al[1][3] = bf2_lo(q11, ah[1][3]);

        int kw = ks * 8 + t;
        #pragma unroll
        for (int n = 0; n < 8; n++) {
            int nb = (n0 + 8 * n + g) * PAD_W + kw;
            uint32_t bh0 = WH[nb], bh1 = WH[nb + 4];
            uint32_t bl0 = WL[nb], bl1 = WL[nb + 4];
            #pragma unroll
            for (int m = 0; m < 2; m++) {
                MMA16816(d[m][n], ah[m][0], ah[m][1], ah[m][2], ah[m][3], bh0, bh1);
                MMA16816(d[m][n], ah[m][0], ah[m][1], ah[m][2], ah[m][3], bl0, bl1);
                MMA16816(d[m][n], al[m][0], al[m][1], al[m][2], al[m][3], bh0, bh1);
            }
        }
    }

    // ---- epilogue: d -> g_Y  (mma D layout: rows {g, g+8} per m) ----
    #pragma unroll
    for (int m = 0; m < 2; m++) {
        int r = base + 16 * m;
        #pragma unroll
        for (int n = 0; n < 8; n++) {
            int c = n0 + 8 * n + 2 * t;
            if (r < nrows)
                *(float2*)(g_Y + (size_t)r * HID + c) = make_float2(d[m][n][0], d[m][n][1]);
            if (r + 8 < nrows)
                *(float2*)(g_Y + (size_t)(r + 8) * HID + c) = make_float2(d[m][n][2], d[m][n][3]);
        }
    }
}

// ------------------- kernel 3: per-edge gather + dot + sigmoid --------------
__global__ __launch_bounds__(256) void edge_kernel(const void* __restrict__ ei,
                                                   const float* __restrict__ Z,
                                                   float* __restrict__ out, int E) {
    const unsigned FULL = 0xFFFFFFFFu;
    int gtid  = blockIdx.x * blockDim.x + threadIdx.x;
    int warp  = gtid >> 5;
    int lane  = gtid & 31;
    int grp   = lane >> 3;
    int sub   = lane & 7;

    long long e0 = (long long)warp * 4;
    if (e0 >= E) return;

    long long myidx = 0;
    int is64 = g_is64;
    if (lane < 8) {
        long long e = e0 + (lane & 3);
        if (e >= E) e = 0;
        size_t off = (lane < 4) ? (size_t)e : (size_t)E + (size_t)e;
        if (is64) myidx = ((const long long*)ei)[off];
        else      myidx = ((const int*)ei)[off];
    }
    long long src = __shfl_sync(FULL, myidx, grp);
    long long dst = __shfl_sync(FULL, myidx, 4 + grp);

    const float4* Ya = (const float4*)(g_Y + (size_t)src * HID);
    const float4* Zb = (const float4*)(Z   + (size_t)dst * HID);

    float4 a0 = Ya[sub];        float4 b0 = Zb[sub];
    float4 a1 = Ya[sub + 8];    float4 b1 = Zb[sub + 8];
    float4 a2 = Ya[sub + 16];   float4 b2 = Zb[sub + 16];
    float4 a3 = Ya[sub + 24];   float4 b3 = Zb[sub + 24];

    float v = a0.x * b0.x + a0.y * b0.y + a0.z * b0.z + a0.w * b0.w;
    v += a1.x * b1.x + a1.y * b1.y + a1.z * b1.z + a1.w * b1.w;
    v += a2.x * b2.x + a2.y * b2.y + a2.z * b2.z + a2.w * b2.w;
    v += a3.x * b3.x + a3.y * b3.y + a3.z * b3.z + a3.w * b3.w;

    v += __shfl_xor_sync(FULL, v, 1);
    v += __shfl_xor_sync(FULL, v, 2);
    v += __shfl_xor_sync(FULL, v, 4);

    float vg = __shfl_sync(FULL, v, lane << 3);
    if (lane < 4) {
        long long e = e0 + lane;
        if (e < E) out[e] = 1.0f / (1.0f + expf(-vg));
    }
}

// ---------------------------------------------------------------------------
extern "C" void kernel_launch(void* const* d_in, const int* in_sizes, int n_in,
                              void* d_out, int out_size) {
    // Map inputs by element count: W = 16384; z = largest; edge_index = the rest.
    int wi = -1;
    for (int i = 0; i < n_in; i++) if (in_sizes[i] == HID * HID) { wi = i; break; }
    int zi = -1;
    for (int i = 0; i < n_in; i++) {
        if (i == wi) continue;
        if (zi < 0 || in_sizes[i] > in_sizes[zi]) zi = i;
    }
    int eii = -1;
    for (int i = 0; i < n_in; i++) if (i != wi && i != zi) { eii = i; break; }

    const float* W  = (const float*)d_in[wi];
    const float* z  = (const float*)d_in[zi];
    const void*  ei = d_in[eii];

    float* out = (float*)d_out;
    int nrows = in_sizes[zi] / HID;
    int E     = in_sizes[eii] / 2;

    symm_kernel<<<64, 256>>>(W, (const int*)ei);

    int smem = 2 * 128 * PAD_W * (int)sizeof(uint32_t);   // 69632 B -> 2 CTAs/SM
    cudaFuncSetAttribute(gemm_mma_kernel, cudaFuncAttributeMaxDynamicSharedMemorySize, smem);
    int gblocks = (nrows + 127) / 128;
    gemm_mma_kernel<<<gblocks, 256, smem>>>(z, nrows);

    int eblocks = (E + 31) / 32;
    edge_kernel<<<eblocks, 256>>>(ei, z, out, E);
}

// round 8
// speedup vs baseline: 1.2395x; 1.1484x over previous
#include <cuda_runtime.h>
#include <cuda_bf16.h>
#include <math.h>
#include <stdint.h>

// ---------------------------------------------------------------------------
// DistMultDecoder: out[e] = sigmoid( z[src_e] . (W + W^T) . z[dst_e] )
//   Wsym = W + W^T (symmetric) ; Y = Z @ Wsym ; out[e] = sigmoid(dot(Y[src], Z[dst]))
// GEMM: mma.sync bf16, 2-term Dekker split  Y = Zh*Wh + Zh*Wl + Zl*Wh.
// A fragments direct from global (registers only); smem = W hi/lo (2 CTAs/SM).
// Edge: 8 lanes/edge, 8 edges/warp, 16 LDG.128 in flight per lane batch.
// ---------------------------------------------------------------------------

#define HID 128
#define MAX_NODES 100000
#define PAD_W 68   // words/row: frag LDS bank = (4g+t) mod 32, conflict-free

__device__ float g_Y[(size_t)MAX_NODES * HID];
__device__ int   g_is64;
__device__ __nv_bfloat16 g_Wh[HID * HID];   // Wsym hi, row-major [n][k]
__device__ __nv_bfloat16 g_Wl[HID * HID];   // Wsym lo

// ------- kernel 1: Wsym = W + W^T -> bf16 hi/lo ; + index-dtype detect ------
__global__ void symm_kernel(const float* __restrict__ W, const int* __restrict__ ei32) {
    if (blockIdx.x == 0 && threadIdx.x == 0) {
        int s = 0;
        #pragma unroll
        for (int i = 1; i < 64; i += 2) s |= ei32[i];
        g_is64 = (s == 0) ? 1 : 0;          // int64 LE small values: odd words all 0
    }
    int i = blockIdx.x * blockDim.x + threadIdx.x;   // 0..16383
    int n = i >> 7, k = i & 127;
    float v = W[n * HID + k] + W[k * HID + n];       // Wsym[n][k]
    __nv_bfloat16 hi = __float2bfloat16(v);
    __nv_bfloat16 lo = __float2bfloat16(v - __bfloat162float(hi));
    g_Wh[i] = hi;
    g_Wl[i] = lo;
}

// ---------------- kernel 2: Y = Z @ Wsym via mma.sync bf16 ------------------
#define MMA16816(D, A0, A1, A2, A3, B0, B1)                                   \
    asm volatile("mma.sync.aligned.m16n8k16.row.col.f32.bf16.bf16.f32 "       \
                 "{%0,%1,%2,%3}, {%4,%5,%6,%7}, {%8,%9}, {%0,%1,%2,%3};"      \
                 : "+f"(D[0]), "+f"(D[1]), "+f"(D[2]), "+f"(D[3])             \
                 : "r"(A0), "r"(A1), "r"(A2), "r"(A3), "r"(B0), "r"(B1))

__device__ __forceinline__ uint32_t bf2_hi(float2 p) {
    __nv_bfloat162 h = __floats2bfloat162_rn(p.x, p.y);
    return *(uint32_t*)&h;
}
__device__ __forceinline__ uint32_t bf2_lo(float2 p, uint32_t hbits) {
    __nv_bfloat162 h = *(__nv_bfloat162*)&hbits;
    __nv_bfloat162 l = __floats2bfloat162_rn(p.x - __bfloat162float(h.x),
                                             p.y - __bfloat162float(h.y));
    return *(uint32_t*)&l;
}

__global__ __launch_bounds__(256, 2) void gemm_mma_kernel(const float* __restrict__ Z, int nrows) {
    extern __shared__ __align__(16) uint32_t sh[];
    uint32_t* WH = sh;                    // 128 x 68 words (bf16x2)
    uint32_t* WL = sh + 128 * PAD_W;

    int tid = threadIdx.x;

    // ---- stage W hi/lo into padded smem (8192 words each, coalesced) ----
    {
        const uint32_t* gwh = (const uint32_t*)g_Wh;
        const uint32_t* gwl = (const uint32_t*)g_Wl;
        #pragma unroll
        for (int i = 0; i < 32; i++) {
            int idx  = tid + 256 * i;        // 0..8191
            int row  = idx >> 6;
            int word = idx & 63;
            WH[row * PAD_W + word] = gwh[idx];
            WL[row * PAD_W + word] = gwl[idx];
        }
    }
    __syncthreads();

    int lane = tid & 31, w = tid >> 5;
    int g = lane >> 2, t = lane & 3;
    int r0 = (w & 3) * 32;        // warp row base within CTA tile
    int n0 = (w >> 2) * 64;       // warp col base

    // Per-thread A rows (clamped for OOB; garbage accumulators never stored)
    int base = blockIdx.x * 128 + r0 + g;
    int rA[4] = { base, base + 8, base + 16, base + 24 };
    const float* zp[4];
    #pragma unroll
    for (int q = 0; q < 4; q++) {
        int r = rA[q] < nrows ? rA[q] : (nrows - 1);
        zp[q] = Z + (size_t)r * HID + 2 * t;
    }

    float d[2][8][4];
    #pragma unroll
    for (int m = 0; m < 2; m++)
        #pragma unroll
        for (int n = 0; n < 8; n++)
            #pragma unroll
            for (int q = 0; q < 4; q++) d[m][n][q] = 0.f;

    #pragma unroll
    for (int ks = 0; ks < 8; ks++) {
        int kb = ks * 16;
        float2 p00 = *(const float2*)(zp[0] + kb);
        float2 p01 = *(const float2*)(zp[0] + kb + 8);
        float2 p10 = *(const float2*)(zp[1] + kb);
        float2 p11 = *(const float2*)(zp[1] + kb + 8);
        float2 q00 = *(const float2*)(zp[2] + kb);
        float2 q01 = *(const float2*)(zp[2] + kb + 8);
        float2 q10 = *(const float2*)(zp[3] + kb);
        float2 q11 = *(const float2*)(zp[3] + kb + 8);

        uint32_t ah[2][4], al[2][4];
        ah[0][0] = bf2_hi(p00);  ah[0][1] = bf2_hi(p10);
        ah[0][2] = bf2_hi(p01);  ah[0][3] = bf2_hi(p11);
        ah[1][0] = bf2_hi(q00);  ah[1][1] = bf2_hi(q10);
        ah[1][2] = bf2_hi(q01);  ah[1][3] = bf2_hi(q11);
        al[0][0] = bf2_lo(p00, ah[0][0]);  al[0][1] = bf2_lo(p10, ah[0][1]);
        al[0][2] = bf2_lo(p01, ah[0][2]);  al[0][3] = bf2_lo(p11, ah[0][3]);
        al[1][0] = bf2_lo(q00, ah[1][0]);  al[1][1] = bf2_lo(q10, ah[1][1]);
        al[1][2] = bf2_lo(q01, ah[1][2]);  al[1][3] = bf2_lo(q11, ah[1][3]);

        int kw = ks * 8 + t;
        #pragma unroll
        for (int n = 0; n < 8; n++) {
            int nb = (n0 + 8 * n + g) * PAD_W + kw;
            uint32_t bh0 = WH[nb], bh1 = WH[nb + 4];
            uint32_t bl0 = WL[nb], bl1 = WL[nb + 4];
            #pragma unroll
            for (int m = 0; m < 2; m++) {
                MMA16816(d[m][n], ah[m][0], ah[m][1], ah[m][2], ah[m][3], bh0, bh1);
                MMA16816(d[m][n], ah[m][0], ah[m][1], ah[m][2], ah[m][3], bl0, bl1);
                MMA16816(d[m][n], al[m][0], al[m][1], al[m][2], al[m][3], bh0, bh1);
            }
        }
    }

    // ---- epilogue: d -> g_Y ----
    #pragma unroll
    for (int m = 0; m < 2; m++) {
        int r = base + 16 * m;
        #pragma unroll
        for (int n = 0; n < 8; n++) {
            int c = n0 + 8 * n + 2 * t;
            if (r < nrows)
                *(float2*)(g_Y + (size_t)r * HID + c) = make_float2(d[m][n][0], d[m][n][1]);
            if (r + 8 < nrows)
                *(float2*)(g_Y + (size_t)(r + 8) * HID + c) = make_float2(d[m][n][2], d[m][n][3]);
        }
    }
}

// ------------------- kernel 3: per-edge gather + dot + sigmoid --------------
// 8 lanes/edge, 8 edges/warp in two 4-edge batches; all 16 LDG.128 per lane
// issued before any reduction -> 2x in-flight loads vs R7.
__global__ __launch_bounds__(256) void edge_kernel(const void* __restrict__ ei,
                                                   const float* __restrict__ Z,
                                                   float* __restrict__ out, int E) {
    const unsigned FULL = 0xFFFFFFFFu;
    int gtid  = blockIdx.x * blockDim.x + threadIdx.x;
    int warp  = gtid >> 5;
    int lane  = gtid & 31;
    int grp   = lane >> 3;       // 0..3
    int sub   = lane & 7;        // 0..7

    long long e0 = (long long)warp * 8;
    if (e0 >= E) return;

    // --- batched index load: lanes 0..7 -> src[e0+l], lanes 8..15 -> dst[e0+l-8]
    long long myidx = 0;
    int is64 = g_is64;
    if (lane < 16) {
        long long e = e0 + (lane & 7);
        if (e >= E) e = 0;
        size_t off = (lane < 8) ? (size_t)e : (size_t)E + (size_t)e;
        if (is64) myidx = ((const long long*)ei)[off];
        else      myidx = ((const int*)ei)[off];
    }
    long long s0 = __shfl_sync(FULL, myidx, grp);         // batch0 src
    long long s1 = __shfl_sync(FULL, myidx, 4 + grp);     // batch1 src
    long long d0 = __shfl_sync(FULL, myidx, 8 + grp);     // batch0 dst
    long long d1 = __shfl_sync(FULL, myidx, 12 + grp);    // batch1 dst

    const float4* Ya0 = (const float4*)(g_Y + (size_t)s0 * HID);
    const float4* Zb0 = (const float4*)(Z   + (size_t)d0 * HID);
    const float4* Ya1 = (const float4*)(g_Y + (size_t)s1 * HID);
    const float4* Zb1 = (const float4*)(Z   + (size_t)d1 * HID);

    // --- 16 independent LDG.128 ---
    float4 a0 = Ya0[sub];       float4 b0 = Zb0[sub];
    float4 a1 = Ya0[sub + 8];   float4 b1 = Zb0[sub + 8];
    float4 a2 = Ya0[sub + 16];  float4 b2 = Zb0[sub + 16];
    float4 a3 = Ya0[sub + 24];  float4 b3 = Zb0[sub + 24];
    float4 c0 = Ya1[sub];       float4 e0v = Zb1[sub];
    float4 c1 = Ya1[sub + 8];   float4 e1v = Zb1[sub + 8];
    float4 c2 = Ya1[sub + 16];  float4 e2v = Zb1[sub + 16];
    float4 c3 = Ya1[sub + 24];  float4 e3v = Zb1[sub + 24];

    float v0 = a0.x * b0.x + a0.y * b0.y + a0.z * b0.z + a0.w * b0.w;
    v0 += a1.x * b1.x + a1.y * b1.y + a1.z * b1.z + a1.w * b1.w;
    v0 += a2.x * b2.x + a2.y * b2.y + a2.z * b2.z + a2.w * b2.w;
    v0 += a3.x * b3.x + a3.y * b3.y + a3.z * b3.z + a3.w * b3.w;

    float v1 = c0.x * e0v.x + c0.y * e0v.y + c0.z * e0v.z + c0.w * e0v.w;
    v1 += c1.x * e1v.x + c1.y * e1v.y + c1.z * e1v.z + c1.w * e1v.w;
    v1 += c2.x * e2v.x + c2.y * e2v.y + c2.z * e2v.z + c2.w * e2v.w;
    v1 += c3.x * e3v.x + c3.y * e3v.y + c3.z * e3v.z + c3.w * e3v.w;

    // --- 3-level reduction within 8-lane groups, both batches ---
    v0 += __shfl_xor_sync(FULL, v0, 1);
    v1 += __shfl_xor_sync(FULL, v1, 1);
    v0 += __shfl_xor_sync(FULL, v0, 2);
    v1 += __shfl_xor_sync(FULL, v1, 2);
    v0 += __shfl_xor_sync(FULL, v0, 4);
    v1 += __shfl_xor_sync(FULL, v1, 4);

    // --- gather: lanes 0..3 <- v0 of groups 0..3 ; lanes 4..7 <- v1 ---
    float vg0 = __shfl_sync(FULL, v0, (lane & 3) << 3);
    float vg1 = __shfl_sync(FULL, v1, (lane & 3) << 3);
    float vg  = (lane < 4) ? vg0 : vg1;

    if (lane < 8) {
        long long e = e0 + lane;
        if (e < E) out[e] = 1.0f / (1.0f + expf(-vg));
    }
}

// ---------------------------------------------------------------------------
extern "C" void kernel_launch(void* const* d_in, const int* in_sizes, int n_in,
                              void* d_out, int out_size) {
    // Map inputs by element count: W = 16384; z = largest; edge_index = the rest.
    int wi = -1;
    for (int i = 0; i < n_in; i++) if (in_sizes[i] == HID * HID) { wi = i; break; }
    int zi = -1;
    for (int i = 0; i < n_in; i++) {
        if (i == wi) continue;
        if (zi < 0 || in_sizes[i] > in_sizes[zi]) zi = i;
    }
    int eii = -1;
    for (int i = 0; i < n_in; i++) if (i != wi && i != zi) { eii = i; break; }

    const float* W  = (const float*)d_in[wi];
    const float* z  = (const float*)d_in[zi];
    const void*  ei = d_in[eii];

    float* out = (float*)d_out;
    int nrows = in_sizes[zi] / HID;
    int E     = in_sizes[eii] / 2;

    symm_kernel<<<64, 256>>>(W, (const int*)ei);

    int smem = 2 * 128 * PAD_W * (int)sizeof(uint32_t);   // 69632 B -> 2 CTAs/SM
    cudaFuncSetAttribute(gemm_mma_kernel, cudaFuncAttributeMaxDynamicSharedMemorySize, smem);
    int gblocks = (nrows + 127) / 128;
    gemm_mma_kernel<<<gblocks, 256, smem>>>(z, nrows);

    // 64 edges per 256-thread block (8 edges per warp)
    int eblocks = (E + 63) / 64;
    edge_kernel<<<eblocks, 256>>>(ei, z, out, E);
}

// round 9
// speedup vs baseline: 1.2409x; 1.0011x over previous
#include <cuda_runtime.h>
#include <cuda_bf16.h>
#include <math.h>
#include <stdint.h>

// ---------------------------------------------------------------------------
// DistMultDecoder: out[e] = sigmoid( z[src_e] . (W + W^T) . z[dst_e] )
//   Wsym = W + W^T (symmetric) ; Y = Z @ Wsym ; out[e] = sigmoid(dot(Y[src], Z[dst]))
// GEMM: mma.sync bf16, 2-term Dekker split  Y = Zh*Wh + Zh*Wl + Zl*Wh.
// Inner loop = 3 independent n-sweeps per k-step (no RAW-chained MMAs).
// Edge: 8 lanes/edge, 8 edges/warp, 16 LDG.128 in flight per lane.
// ---------------------------------------------------------------------------

#define HID 128
#define MAX_NODES 100000
#define PAD_W 68   // words/row: frag LDS bank = (4g+t) mod 32, conflict-free

__device__ float g_Y[(size_t)MAX_NODES * HID];
__device__ int   g_is64;
__device__ __nv_bfloat16 g_Wh[HID * HID];   // Wsym hi, row-major [n][k]
__device__ __nv_bfloat16 g_Wl[HID * HID];   // Wsym lo

// ------- kernel 1: Wsym = W + W^T -> bf16 hi/lo ; + index-dtype detect ------
__global__ void symm_kernel(const float* __restrict__ W, const int* __restrict__ ei32) {
    if (blockIdx.x == 0 && threadIdx.x == 0) {
        int s = 0;
        #pragma unroll
        for (int i = 1; i < 64; i += 2) s |= ei32[i];
        g_is64 = (s == 0) ? 1 : 0;          // int64 LE small values: odd words all 0
    }
    int i = blockIdx.x * blockDim.x + threadIdx.x;   // 0..16383
    int n = i >> 7, k = i & 127;
    float v = W[n * HID + k] + W[k * HID + n];       // Wsym[n][k]
    __nv_bfloat16 hi = __float2bfloat16(v);
    __nv_bfloat16 lo = __float2bfloat16(v - __bfloat162float(hi));
    g_Wh[i] = hi;
    g_Wl[i] = lo;
}

// ---------------- kernel 2: Y = Z @ Wsym via mma.sync bf16 ------------------
#define MMA16816(D, A0, A1, A2, A3, B0, B1)                                   \
    asm volatile("mma.sync.aligned.m16n8k16.row.col.f32.bf16.bf16.f32 "       \
                 "{%0,%1,%2,%3}, {%4,%5,%6,%7}, {%8,%9}, {%0,%1,%2,%3};"      \
                 : "+f"(D[0]), "+f"(D[1]), "+f"(D[2]), "+f"(D[3])             \
                 : "r"(A0), "r"(A1), "r"(A2), "r"(A3), "r"(B0), "r"(B1))

__device__ __forceinline__ uint32_t bf2_hi(float2 p) {
    __nv_bfloat162 h = __floats2bfloat162_rn(p.x, p.y);
    return *(uint32_t*)&h;
}
__device__ __forceinline__ uint32_t bf2_lo(float2 p, uint32_t hbits) {
    __nv_bfloat162 h = *(__nv_bfloat162*)&hbits;
    __nv_bfloat162 l = __floats2bfloat162_rn(p.x - __bfloat162float(h.x),
                                             p.y - __bfloat162float(h.y));
    return *(uint32_t*)&l;
}

__global__ __launch_bounds__(256, 2) void gemm_mma_kernel(const float* __restrict__ Z, int nrows) {
    extern __shared__ __align__(16) uint32_t sh[];
    uint32_t* WH = sh;                    // 128 x 68 words (bf16x2)
    uint32_t* WL = sh + 128 * PAD_W;

    int tid = threadIdx.x;

    // ---- stage W hi/lo into padded smem (8192 words each, coalesced) ----
    {
        const uint32_t* gwh = (const uint32_t*)g_Wh;
        const uint32_t* gwl = (const uint32_t*)g_Wl;
        #pragma unroll
        for (int i = 0; i < 32; i++) {
            int idx  = tid + 256 * i;        // 0..8191
            int row  = idx >> 6;
            int word = idx & 63;
            WH[row * PAD_W + word] = gwh[idx];
            WL[row * PAD_W + word] = gwl[idx];
        }
    }
    __syncthreads();

    int lane = tid & 31, w = tid >> 5;
    int g = lane >> 2, t = lane & 3;
    int r0 = (w & 3) * 32;        // warp row base within CTA tile
    int n0 = (w >> 2) * 64;       // warp col base

    // Per-thread A rows (clamped for OOB; garbage accumulators never stored)
    int base = blockIdx.x * 128 + r0 + g;
    int rA[4] = { base, base + 8, base + 16, base + 24 };
    const float* zp[4];
    #pragma unroll
    for (int q = 0; q < 4; q++) {
        int r = rA[q] < nrows ? rA[q] : (nrows - 1);
        zp[q] = Z + (size_t)r * HID + 2 * t;
    }

    float d[2][8][4];
    #pragma unroll
    for (int m = 0; m < 2; m++)
        #pragma unroll
        for (int n = 0; n < 8; n++)
            #pragma unroll
            for (int q = 0; q < 4; q++) d[m][n][q] = 0.f;

    #pragma unroll
    for (int ks = 0; ks < 8; ks++) {
        int kb = ks * 16;
        float2 p00 = *(const float2*)(zp[0] + kb);
        float2 p01 = *(const float2*)(zp[0] + kb + 8);
        float2 p10 = *(const float2*)(zp[1] + kb);
        float2 p11 = *(const float2*)(zp[1] + kb + 8);
        float2 q00 = *(const float2*)(zp[2] + kb);
        float2 q01 = *(const float2*)(zp[2] + kb + 8);
        float2 q10 = *(const float2*)(zp[3] + kb);
        float2 q11 = *(const float2*)(zp[3] + kb + 8);

        uint32_t ah[2][4], al[2][4];
        ah[0][0] = bf2_hi(p00);  ah[0][1] = bf2_hi(p10);
        ah[0][2] = bf2_hi(p01);  ah[0][3] = bf2_hi(p11);
        ah[1][0] = bf2_hi(q00);  ah[1][1] = bf2_hi(q10);
        ah[1][2] = bf2_hi(q01);  ah[1][3] = bf2_hi(q11);
        al[0][0] = bf2_lo(p00, ah[0][0]);  al[0][1] = bf2_lo(p10, ah[0][1]);
        al[0][2] = bf2_lo(p01, ah[0][2]);  al[0][3] = bf2_lo(p11, ah[0][3]);
        al[1][0] = bf2_lo(q00, ah[1][0]);  al[1][1] = bf2_lo(q10, ah[1][1]);
        al[1][2] = bf2_lo(q01, ah[1][2]);  al[1][3] = bf2_lo(q11, ah[1][3]);

        int kw = ks * 8 + t;

        // ---- pass 1: hi(A) * hi(B) -- 16 independent MMAs ----
        #pragma unroll
        for (int n = 0; n < 8; n++) {
            int nb = (n0 + 8 * n + g) * PAD_W + kw;
            uint32_t bh0 = WH[nb], bh1 = WH[nb + 4];
            MMA16816(d[0][n], ah[0][0], ah[0][1], ah[0][2], ah[0][3], bh0, bh1);
            MMA16816(d[1][n], ah[1][0], ah[1][1], ah[1][2], ah[1][3], bh0, bh1);
        }
        // ---- pass 2: hi(A) * lo(B) ----
        #pragma unroll
        for (int n = 0; n < 8; n++) {
            int nb = (n0 + 8 * n + g) * PAD_W + kw;
            uint32_t bl0 = WL[nb], bl1 = WL[nb + 4];
            MMA16816(d[0][n], ah[0][0], ah[0][1], ah[0][2], ah[0][3], bl0, bl1);
            MMA16816(d[1][n], ah[1][0], ah[1][1], ah[1][2], ah[1][3], bl0, bl1);
        }
        // ---- pass 3: lo(A) * hi(B) ----
        #pragma unroll
        for (int n = 0; n < 8; n++) {
            int nb = (n0 + 8 * n + g) * PAD_W + kw;
            uint32_t bh0 = WH[nb], bh1 = WH[nb + 4];
            MMA16816(d[0][n], al[0][0], al[0][1], al[0][2], al[0][3], bh0, bh1);
            MMA16816(d[1][n], al[1][0], al[1][1], al[1][2], al[1][3], bh0, bh1);
        }
    }

    // ---- epilogue: d -> g_Y ----
    #pragma unroll
    for (int m = 0; m < 2; m++) {
        int r = base + 16 * m;
        #pragma unroll
        for (int n = 0; n < 8; n++) {
            int c = n0 + 8 * n + 2 * t;
            if (r < nrows)
                *(float2*)(g_Y + (size_t)r * HID + c) = make_float2(d[m][n][0], d[m][n][1]);
            if (r + 8 < nrows)
                *(float2*)(g_Y + (size_t)(r + 8) * HID + c) = make_float2(d[m][n][2], d[m][n][3]);
        }
    }
}

// ------------------- kernel 3: per-edge gather + dot + sigmoid --------------
__global__ __launch_bounds__(256) void edge_kernel(const void* __restrict__ ei,
                                                   const float* __restrict__ Z,
                                                   float* __restrict__ out, int E) {
    const unsigned FULL = 0xFFFFFFFFu;
    int gtid  = blockIdx.x * blockDim.x + threadIdx.x;
    int warp  = gtid >> 5;
    int lane  = gtid & 31;
    int grp   = lane >> 3;       // 0..3
    int sub   = lane & 7;        // 0..7

    long long e0 = (long long)warp * 8;
    if (e0 >= E) return;

    long long myidx = 0;
    int is64 = g_is64;
    if (lane < 16) {
        long long e = e0 + (lane & 7);
        if (e >= E) e = 0;
        size_t off = (lane < 8) ? (size_t)e : (size_t)E + (size_t)e;
        if (is64) myidx = ((const long long*)ei)[off];
        else      myidx = ((const int*)ei)[off];
    }
    long long s0 = __shfl_sync(FULL, myidx, grp);
    long long s1 = __shfl_sync(FULL, myidx, 4 + grp);
    long long d0 = __shfl_sync(FULL, myidx, 8 + grp);
    long long d1 = __shfl_sync(FULL, myidx, 12 + grp);

    const float4* Ya0 = (const float4*)(g_Y + (size_t)s0 * HID);
    const float4* Zb0 = (const float4*)(Z   + (size_t)d0 * HID);
    const float4* Ya1 = (const float4*)(g_Y + (size_t)s1 * HID);
    const float4* Zb1 = (const float4*)(Z   + (size_t)d1 * HID);

    float4 a0 = Ya0[sub];       float4 b0 = Zb0[sub];
    float4 a1 = Ya0[sub + 8];   float4 b1 = Zb0[sub + 8];
    float4 a2 = Ya0[sub + 16];  float4 b2 = Zb0[sub + 16];
    float4 a3 = Ya0[sub + 24];  float4 b3 = Zb0[sub + 24];
    float4 c0 = Ya1[sub];       float4 e0v = Zb1[sub];
    float4 c1 = Ya1[sub + 8];   float4 e1v = Zb1[sub + 8];
    float4 c2 = Ya1[sub + 16];  float4 e2v = Zb1[sub + 16];
    float4 c3 = Ya1[sub + 24];  float4 e3v = Zb1[sub + 24];

    float v0 = a0.x * b0.x + a0.y * b0.y + a0.z * b0.z + a0.w * b0.w;
    v0 += a1.x * b1.x + a1.y * b1.y + a1.z * b1.z + a1.w * b1.w;
    v0 += a2.x * b2.x + a2.y * b2.y + a2.z * b2.z + a2.w * b2.w;
    v0 += a3.x * b3.x + a3.y * b3.y + a3.z * b3.z + a3.w * b3.w;

    float v1 = c0.x * e0v.x + c0.y * e0v.y + c0.z * e0v.z + c0.w * e0v.w;
    v1 += c1.x * e1v.x + c1.y * e1v.y + c1.z * e1v.z + c1.w * e1v.w;
    v1 += c2.x * e2v.x + c2.y * e2v.y + c2.z * e2v.z + c2.w * e2v.w;
    v1 += c3.x * e3v.x + c3.y * e3v.y + c3.z * e3v.z + c3.w * e3v.w;

    v0 += __shfl_xor_sync(FULL, v0, 1);
    v1 += __shfl_xor_sync(FULL, v1, 1);
    v0 += __shfl_xor_sync(FULL, v0, 2);
    v1 += __shfl_xor_sync(FULL, v1, 2);
    v0 += __shfl_xor_sync(FULL, v0, 4);
    v1 += __shfl_xor_sync(FULL, v1, 4);

    float vg0 = __shfl_sync(FULL, v0, (lane & 3) << 3);
    float vg1 = __shfl_sync(FULL, v1, (lane & 3) << 3);
    float vg  = (lane < 4) ? vg0 : vg1;

    if (lane < 8) {
        long long e = e0 + lane;
        if (e < E) out[e] = 1.0f / (1.0f + expf(-vg));
    }
}

// ---------------------------------------------------------------------------
extern "C" void kernel_launch(void* const* d_in, const int* in_sizes, int n_in,
                              void* d_out, int out_size) {
    // Map inputs by element count: W = 16384; z = largest; edge_index = the rest.
    int wi = -1;
    for (int i = 0; i < n_in; i++) if (in_sizes[i] == HID * HID) { wi = i; break; }
    int zi = -1;
    for (int i = 0; i < n_in; i++) {
        if (i == wi) continue;
        if (zi < 0 || in_sizes[i] > in_sizes[zi]) zi = i;
    }
    int eii = -1;
    for (int i = 0; i < n_in; i++) if (i != wi && i != zi) { eii = i; break; }

    const float* W  = (const float*)d_in[wi];
    const float* z  = (const float*)d_in[zi];
    const void*  ei = d_in[eii];

    float* out = (float*)d_out;
    int nrows = in_sizes[zi] / HID;
    int E     = in_sizes[eii] / 2;

    symm_kernel<<<64, 256>>>(W, (const int*)ei);

    int smem = 2 * 128 * PAD_W * (int)sizeof(uint32_t);   // 69632 B -> 2 CTAs/SM
    cudaFuncSetAttribute(gemm_mma_kernel, cudaFuncAttributeMaxDynamicSharedMemorySize, smem);
    int gblocks = (nrows + 127) / 128;
    gemm_mma_kernel<<<gblocks, 256, smem>>>(z, nrows);

    int eblocks = (E + 63) / 64;
    edge_kernel<<<eblocks, 256>>>(ei, z, out, E);
}